// round 2
// baseline (speedup 1.0000x reference)
#include <cuda_runtime.h>

#define BB 4
#define NN 100000
#define MM 64
#define TPB 256

__global__ __launch_bounds__(TPB)
void roihead_kernel(const float4* __restrict__ proposals,   // [B,N] of float4
                    const float4* __restrict__ gt,          // [B,M] of float4
                    const float4* __restrict__ deltas,      // [B,N] of float4
                    float* __restrict__ out)                // 3.6M floats
{
    __shared__ float4 sg[MM];
    __shared__ float  sArea[MM];

    const int b   = blockIdx.y;
    const int tid = threadIdx.x;

    if (tid < MM) {
        float4 g = gt[b * MM + tid];
        sg[tid] = g;
        sArea[tid] = __fmul_rn(__fsub_rn(g.z, g.x), __fsub_rn(g.w, g.y));
    }
    __syncthreads();

    const int n = blockIdx.x * TPB + tid;
    if (n >= NN) return;

    const float4 p = proposals[b * NN + n];
    const float Ap = __fmul_rn(__fsub_rn(p.z, p.x), __fsub_rn(p.w, p.y));

    // ---- Matcher: argmax_i IoU(gt_i, p), first-max-wins, bit-exact IoU ----
    float bestv = -1.0f;
    int   besti = 0;
    #pragma unroll 8
    for (int i = 0; i < MM; i++) {
        const float4 g = sg[i];
        const float ltx = fmaxf(g.x, p.x);
        const float lty = fmaxf(g.y, p.y);
        const float rbx = fminf(g.z, p.z);
        const float rby = fminf(g.w, p.w);
        const float wx  = fmaxf(__fsub_rn(rbx, ltx), 0.0f);
        const float wy  = fmaxf(__fsub_rn(rby, lty), 0.0f);
        const float inter = __fmul_rn(wx, wy);
        const float denom = __fsub_rn(__fadd_rn(sArea[i], Ap), inter);
        const float iou   = __fdiv_rn(inter, denom);
        if (iou > bestv) { bestv = iou; besti = i; }
    }

    // FG_THRESH == BG_THRESH == 0.5 -> BETWEEN(-2) is unreachable.
    const int match = (bestv < 0.5f) ? -1 : besti;
    const int gi    = (match < 0) ? 0 : besti;   // jnp.clip(matches, 0)

    // ---- BoxCoder.encode against matched (clamped) gt ----
    const float aw = p.z - p.x;
    const float ah = p.w - p.y;
    const float ax = p.x + 0.5f * aw;
    const float ay = p.y + 0.5f * ah;

    const float4 mg = sg[gi];
    const float gw = fmaxf(mg.z - mg.x, 1.0f);   // clip(.., 1.0)
    const float gh = fmaxf(mg.w - mg.y, 1.0f);
    const float gx = mg.x + 0.5f * gw;
    const float gy = mg.y + 0.5f * gh;

    float4 tgt;
    tgt.x = ((gx - ax) / aw) / 0.1f;
    tgt.y = ((gy - ay) / ah) / 0.1f;
    tgt.z = logf(gw / aw) / 0.2f;
    tgt.w = logf(gh / ah) / 0.2f;

    // ---- BoxCoder.decode for predicted deltas ----
    const float4 d = deltas[b * NN + n];
    const float dx = d.x * 0.1f;
    const float dy = d.y * 0.1f;
    const float dw = d.z * 0.2f;
    const float dh = d.w * 0.2f;
    const float cx = ax + dx * aw;
    const float cy = ay + dy * ah;
    const float pw = expf(dw) * aw;
    const float ph = expf(dh) * ah;

    float4 dec;
    dec.x = cx - 0.5f * pw;
    dec.y = cy - 0.5f * ph;
    dec.z = cx + 0.5f * pw;
    dec.w = cy + 0.5f * ph;

    // ---- Outputs: decoded [B,N,4] | targets [B,N,4] | matches [B,N] ----
    const int idx = b * NN + n;
    float4* out_dec = (float4*)out;
    float4* out_tgt = (float4*)(out + 4 * BB * NN);
    float*  out_mat = out + 8 * BB * NN;

    out_dec[idx] = dec;
    out_tgt[idx] = tgt;
    out_mat[idx] = (float)match;
}

extern "C" void kernel_launch(void* const* d_in, const int* in_sizes, int n_in,
                              void* d_out, int out_size)
{
    const float4* proposals = (const float4*)d_in[0];
    const float4* gt        = (const float4*)d_in[1];
    const float4* deltas    = (const float4*)d_in[2];
    float* out = (float*)d_out;

    dim3 grid((NN + TPB - 1) / TPB, BB);
    roihead_kernel<<<grid, TPB>>>(proposals, gt, deltas, out);
}

// round 3
// speedup vs baseline: 1.5052x; 1.5052x over previous
#include <cuda_runtime.h>

#define BB 4
#define NN 100000
#define MM 64
#define TPB 256
#define HALF (NN / 2)   // NN is even: each thread handles 2 proposals

// Compute intersection and IoU-denominator (bit-exact same op order as reference:
// clamp-after-sub, denom = (Ag + Ap) - inter).
__device__ __forceinline__ void iou_id(const float4 g, const float S,
                                       const float4 p, const float Ap,
                                       float& inter, float& denom)
{
    const float ltx = fmaxf(g.x, p.x);
    const float lty = fmaxf(g.y, p.y);
    const float rbx = fminf(g.z, p.z);
    const float rby = fminf(g.w, p.w);
    const float wx  = fmaxf(__fsub_rn(rbx, ltx), 0.0f);
    const float wy  = fmaxf(__fsub_rn(rby, lty), 0.0f);
    inter = __fmul_rn(wx, wy);
    denom = __fsub_rn(__fadd_rn(S, Ap), inter);
}

// Encode targets + decode deltas + write all three outputs for one proposal.
__device__ __forceinline__ void epilogue(const float4 p, const float4 d, const float4 mg,
                                         const int match, const int idx,
                                         float* __restrict__ out)
{
    const float aw = p.z - p.x;
    const float ah = p.w - p.y;
    const float ax = p.x + 0.5f * aw;
    const float ay = p.y + 0.5f * ah;
    const float rw = __fdiv_rn(1.0f, aw);
    const float rh = __fdiv_rn(1.0f, ah);

    // encode vs matched (clamped) gt
    const float gw = fmaxf(mg.z - mg.x, 1.0f);
    const float gh = fmaxf(mg.w - mg.y, 1.0f);
    const float gx = mg.x + 0.5f * gw;
    const float gy = mg.y + 0.5f * gh;

    float4 tgt;
    tgt.x = (gx - ax) * rw * 10.0f;   // / 0.1
    tgt.y = (gy - ay) * rh * 10.0f;
    tgt.z = __logf(gw * rw) * 5.0f;   // / 0.2
    tgt.w = __logf(gh * rh) * 5.0f;

    // decode predicted deltas
    const float cx = ax + (d.x * 0.1f) * aw;
    const float cy = ay + (d.y * 0.1f) * ah;
    const float pw = __expf(d.z * 0.2f) * aw;
    const float ph = __expf(d.w * 0.2f) * ah;

    float4 dec;
    dec.x = cx - 0.5f * pw;
    dec.y = cy - 0.5f * ph;
    dec.z = cx + 0.5f * pw;
    dec.w = cy + 0.5f * ph;

    ((float4*)out)[idx] = dec;                       // decoded  [B,N,4]
    ((float4*)(out + 4 * BB * NN))[idx] = tgt;       // targets  [B,N,4]
    (out + 8 * BB * NN)[idx] = (float)match;         // matches  [B,N]
}

__global__ __launch_bounds__(TPB)
void roihead_kernel(const float4* __restrict__ proposals,
                    const float4* __restrict__ gt,
                    const float4* __restrict__ deltas,
                    float* __restrict__ out)
{
    __shared__ float4 sg[MM];
    __shared__ float  sS[MM];

    const int b   = blockIdx.y;
    const int tid = threadIdx.x;

    if (tid < MM) {
        const float4 g = gt[b * MM + tid];
        sg[tid] = g;
        sS[tid] = __fmul_rn(__fsub_rn(g.z, g.x), __fsub_rn(g.w, g.y));
    }
    __syncthreads();

    const int t = blockIdx.x * TPB + tid;
    if (t >= HALF) return;
    const int n0 = 2 * t;
    const int n1 = n0 + 1;

    const float4 p0 = proposals[b * NN + n0];
    const float4 p1 = proposals[b * NN + n1];
    const float Ap0 = __fmul_rn(__fsub_rn(p0.z, p0.x), __fsub_rn(p0.w, p0.y));
    const float Ap1 = __fmul_rn(__fsub_rn(p1.z, p1.x), __fsub_rn(p1.w, p1.y));

    // ---- division-free argmax over gt boxes (first-max-wins) ----
    float bI0, bD0, bI1, bD1;
    int bi0 = 0, bi1 = 0;
    {
        const float4 g = sg[0];
        const float  S = sS[0];
        iou_id(g, S, p0, Ap0, bI0, bD0);
        iou_id(g, S, p1, Ap1, bI1, bD1);
    }

    #pragma unroll 16
    for (int i = 1; i < MM; i++) {
        const float4 g = sg[i];
        const float  S = sS[i];

        float in0, dn0, in1, dn1;
        iou_id(g, S, p0, Ap0, in0, dn0);
        iou_id(g, S, p1, Ap1, in1, dn1);

        // iou_i > iou_best  <=>  inter_i * bestDenom > bestInter * denom_i (denoms > 0)
        if (__fmul_rn(in0, bD0) > __fmul_rn(bI0, dn0)) { bI0 = in0; bD0 = dn0; bi0 = i; }
        if (__fmul_rn(in1, bD1) > __fmul_rn(bI1, dn1)) { bI1 = in1; bD1 = dn1; bi1 = i; }
    }

    // Exact division only for the winner -> threshold decision matches reference bitwise.
    const float iou0 = __fdiv_rn(bI0, bD0);
    const float iou1 = __fdiv_rn(bI1, bD1);

    // FG_THRESH == BG_THRESH == 0.5: BETWEEN(-2) unreachable.
    const int m0 = (iou0 < 0.5f) ? -1 : bi0;
    const int m1 = (iou1 < 0.5f) ? -1 : bi1;

    const float4 mg0 = sg[(m0 < 0) ? 0 : bi0];   // jnp.clip(matches, 0) gather
    const float4 mg1 = sg[(m1 < 0) ? 0 : bi1];

    const float4 d0 = deltas[b * NN + n0];
    const float4 d1 = deltas[b * NN + n1];

    epilogue(p0, d0, mg0, m0, b * NN + n0, out);
    epilogue(p1, d1, mg1, m1, b * NN + n1, out);
}

extern "C" void kernel_launch(void* const* d_in, const int* in_sizes, int n_in,
                              void* d_out, int out_size)
{
    const float4* proposals = (const float4*)d_in[0];
    const float4* gt        = (const float4*)d_in[1];
    const float4* deltas    = (const float4*)d_in[2];
    float* out = (float*)d_out;

    dim3 grid((HALF + TPB - 1) / TPB, BB);
    roihead_kernel<<<grid, TPB>>>(proposals, gt, deltas, out);
}

// round 5
// speedup vs baseline: 2.3819x; 1.5824x over previous
#include <cuda_runtime.h>

#define BB    4
#define NN    100000
#define MM    64
#define TPB   256
#define NBLK  185          // blocks per image; 185*4 = 740 = 148 SMs * 5 CTAs (one wave)
#define CHUNK 541          // ceil(100000/185); 541 = 2*256 + 29
#define REM   (CHUNK - 2 * TPB)   // 29

// Intersection + IoU denominator, bit-exact op order vs reference
// (clamp-after-sub, denom = (Ag + Ap) - inter).
__device__ __forceinline__ void iou_id(const float4 g, const float S,
                                       const float4 p, const float Ap,
                                       float& inter, float& denom)
{
    const float ltx = fmaxf(g.x, p.x);
    const float lty = fmaxf(g.y, p.y);
    const float rbx = fminf(g.z, p.z);
    const float rby = fminf(g.w, p.w);
    const float wx  = fmaxf(__fsub_rn(rbx, ltx), 0.0f);
    const float wy  = fmaxf(__fsub_rn(rby, lty), 0.0f);
    inter = __fmul_rn(wx, wy);
    denom = __fsub_rn(__fadd_rn(S, Ap), inter);
}

// Encode targets + decode deltas + write all three outputs for one proposal.
__device__ __forceinline__ void epilogue(const float4 p, const float4 d, const float4 mg,
                                         const int match, const int idx,
                                         float* __restrict__ out)
{
    const float aw = p.z - p.x;
    const float ah = p.w - p.y;
    const float ax = p.x + 0.5f * aw;
    const float ay = p.y + 0.5f * ah;
    const float rw = __fdiv_rn(1.0f, aw);
    const float rh = __fdiv_rn(1.0f, ah);

    const float gw = fmaxf(mg.z - mg.x, 1.0f);
    const float gh = fmaxf(mg.w - mg.y, 1.0f);
    const float gx = mg.x + 0.5f * gw;
    const float gy = mg.y + 0.5f * gh;

    float4 tgt;
    tgt.x = (gx - ax) * rw * 10.0f;   // / 0.1
    tgt.y = (gy - ay) * rh * 10.0f;
    tgt.z = __logf(gw * rw) * 5.0f;   // / 0.2
    tgt.w = __logf(gh * rh) * 5.0f;

    const float cx = ax + (d.x * 0.1f) * aw;
    const float cy = ay + (d.y * 0.1f) * ah;
    const float pw = __expf(d.z * 0.2f) * aw;
    const float ph = __expf(d.w * 0.2f) * ah;

    float4 dec;
    dec.x = cx - 0.5f * pw;
    dec.y = cy - 0.5f * ph;
    dec.z = cx + 0.5f * pw;
    dec.w = cy + 0.5f * ph;

    ((float4*)out)[idx] = dec;                       // decoded  [B,N,4]
    ((float4*)(out + 4 * BB * NN))[idx] = tgt;       // targets  [B,N,4]
    (out + 8 * BB * NN)[idx] = (float)match;         // matches  [B,N]
}

// Single-proposal matcher + epilogue (remainder lanes).
__device__ __forceinline__ void process_one(const float4* __restrict__ prop_b,
                                            const float4* __restrict__ del_b,
                                            const float4* __restrict__ sg,
                                            const float*  __restrict__ sS,
                                            const int n, const int bofs,
                                            float* __restrict__ out)
{
    const float4 p  = prop_b[n];
    const float  Ap = __fmul_rn(__fsub_rn(p.z, p.x), __fsub_rn(p.w, p.y));

    float bI, bD;
    int   bi = 0;
    iou_id(sg[0], sS[0], p, Ap, bI, bD);

    #pragma unroll 16
    for (int i = 1; i < MM; i++) {
        float in, dn;
        iou_id(sg[i], sS[i], p, Ap, in, dn);
        if (__fmul_rn(in, bD) > __fmul_rn(bI, dn)) { bI = in; bD = dn; bi = i; }
    }

    const float iou = __fdiv_rn(bI, bD);
    const int   m   = (iou < 0.5f) ? -1 : bi;
    const float4 mg = sg[(m < 0) ? 0 : bi];
    epilogue(p, del_b[n], mg, m, bofs + n, out);
}

__global__ __launch_bounds__(TPB, 5)
void roihead_kernel(const float4* __restrict__ proposals,
                    const float4* __restrict__ gt,
                    const float4* __restrict__ deltas,
                    float* __restrict__ out)
{
    __shared__ float4 sg[MM];
    __shared__ float  sS[MM];

    const int b   = blockIdx.y;
    const int tid = threadIdx.x;

    if (tid < MM) {
        const float4 g = gt[b * MM + tid];
        sg[tid] = g;
        sS[tid] = __fmul_rn(__fsub_rn(g.z, g.x), __fsub_rn(g.w, g.y));
    }
    __syncthreads();

    const int base = blockIdx.x * CHUNK;
    const int bofs = b * NN;
    const float4* prop_b = proposals + bofs;
    const float4* del_b  = deltas    + bofs;

    // ---- pair phase: 2 proposals per thread, gt LDS shared across both ----
    {
        const int  n0    = base + tid;              // always < NN (max 99799)
        const int  n1raw = base + TPB + tid;
        const bool v1    = (n1raw < NN);
        const int  n1    = v1 ? n1raw : n0;

        const float4 p0 = prop_b[n0];
        const float4 p1 = prop_b[n1];
        const float Ap0 = __fmul_rn(__fsub_rn(p0.z, p0.x), __fsub_rn(p0.w, p0.y));
        const float Ap1 = __fmul_rn(__fsub_rn(p1.z, p1.x), __fsub_rn(p1.w, p1.y));

        float bI0, bD0, bI1, bD1;
        int   bi0 = 0, bi1 = 0;
        {
            const float4 g = sg[0];
            const float  S = sS[0];
            iou_id(g, S, p0, Ap0, bI0, bD0);
            iou_id(g, S, p1, Ap1, bI1, bD1);
        }

        #pragma unroll 16
        for (int i = 1; i < MM; i++) {
            const float4 g = sg[i];
            const float  S = sS[i];

            float in0, dn0, in1, dn1;
            iou_id(g, S, p0, Ap0, in0, dn0);
            iou_id(g, S, p1, Ap1, in1, dn1);

            // iou_i > iou_best  <=>  inter_i * bestDenom > bestInter * denom_i
            if (__fmul_rn(in0, bD0) > __fmul_rn(bI0, dn0)) { bI0 = in0; bD0 = dn0; bi0 = i; }
            if (__fmul_rn(in1, bD1) > __fmul_rn(bI1, dn1)) { bI1 = in1; bD1 = dn1; bi1 = i; }
        }

        const float iou0 = __fdiv_rn(bI0, bD0);
        const float iou1 = __fdiv_rn(bI1, bD1);

        // FG_THRESH == BG_THRESH == 0.5 -> BETWEEN(-2) unreachable.
        const int m0 = (iou0 < 0.5f) ? -1 : bi0;
        const int m1 = (iou1 < 0.5f) ? -1 : bi1;

        const float4 mg0 = sg[(m0 < 0) ? 0 : bi0];
        const float4 mg1 = sg[(m1 < 0) ? 0 : bi1];

        epilogue(p0, del_b[n0], mg0, m0, bofs + n0, out);
        if (v1)
            epilogue(p1, del_b[n1], mg1, m1, bofs + n1, out);
    }

    // ---- remainder phase: 29 lanes handle one more proposal each ----
    if (tid < REM) {
        const int n2 = base + 2 * TPB + tid;
        if (n2 < NN)
            process_one(prop_b, del_b, sg, sS, n2, bofs, out);
    }
}

extern "C" void kernel_launch(void* const* d_in, const int* in_sizes, int n_in,
                              void* d_out, int out_size)
{
    const float4* proposals = (const float4*)d_in[0];
    const float4* gt        = (const float4*)d_in[1];
    const float4* deltas    = (const float4*)d_in[2];
    float* out = (float*)d_out;

    dim3 grid(NBLK, BB);
    roihead_kernel<<<grid, TPB>>>(proposals, gt, deltas, out);
}

// round 6
// speedup vs baseline: 2.5795x; 1.0830x over previous
#include <cuda_runtime.h>

#define BB    4
#define NN    100000
#define MM    64
#define HM    32           // half of MM
#define TPB   256
#define BPI   148          // blocks per image; grid = 148*4 = 592 = 148 SMs * 4 CTAs (one wave)
#define CHUNK 676          // ceil(100000/148); 676 = 2*256 + 164
#define REM   (CHUNK - 2 * TPB)   // 164

// Intersection + IoU denominator, bit-exact op order vs reference
// (clamp-after-sub, denom = (Ag + Ap) - inter).
__device__ __forceinline__ void iou_id(const float4 g, const float S,
                                       const float4 p, const float Ap,
                                       float& inter, float& denom)
{
    const float ltx = fmaxf(g.x, p.x);
    const float lty = fmaxf(g.y, p.y);
    const float rbx = fminf(g.z, p.z);
    const float rby = fminf(g.w, p.w);
    const float wx  = fmaxf(__fsub_rn(rbx, ltx), 0.0f);
    const float wy  = fmaxf(__fsub_rn(rby, lty), 0.0f);
    inter = __fmul_rn(wx, wy);
    denom = __fsub_rn(__fadd_rn(S, Ap), inter);
}

struct Best { float I, D; int i; };

// iou_new > iou_best  <=>  in * b.D > b.I * dn   (denoms > 0); strict > keeps first max.
__device__ __forceinline__ void upd(Best& b, const float in, const float dn, const int i)
{
    const bool t = __fmul_rn(in, b.D) > __fmul_rn(b.I, dn);
    b.I = t ? in : b.I;
    b.D = t ? dn : b.D;
    b.i = t ? i  : b.i;
}

// Merge two half-range bests: upper half wins only on STRICT greater (first-max-wins).
__device__ __forceinline__ Best merge(const Best lo, const Best hi)
{
    const bool t = __fmul_rn(hi.I, lo.D) > __fmul_rn(lo.I, hi.D);
    Best w;
    w.I = t ? hi.I : lo.I;
    w.D = t ? hi.D : lo.D;
    w.i = t ? hi.i : lo.i;
    return w;
}

// Encode targets + decode deltas + write all three outputs for one proposal.
__device__ __forceinline__ void epilogue(const float4 p, const float4 d, const float4 mg,
                                         const int match, const int idx,
                                         float* __restrict__ out)
{
    const float aw = p.z - p.x;
    const float ah = p.w - p.y;
    const float ax = p.x + 0.5f * aw;
    const float ay = p.y + 0.5f * ah;
    const float rw = __fdividef(1.0f, aw);   // fast rcp: outputs only need 1e-3
    const float rh = __fdividef(1.0f, ah);

    const float gw = fmaxf(mg.z - mg.x, 1.0f);
    const float gh = fmaxf(mg.w - mg.y, 1.0f);
    const float gx = mg.x + 0.5f * gw;
    const float gy = mg.y + 0.5f * gh;

    float4 tgt;
    tgt.x = (gx - ax) * rw * 10.0f;   // / 0.1
    tgt.y = (gy - ay) * rh * 10.0f;
    tgt.z = __logf(gw * rw) * 5.0f;   // / 0.2
    tgt.w = __logf(gh * rh) * 5.0f;

    const float cx = ax + (d.x * 0.1f) * aw;
    const float cy = ay + (d.y * 0.1f) * ah;
    const float pw = __expf(d.z * 0.2f) * aw;
    const float ph = __expf(d.w * 0.2f) * ah;

    float4 dec;
    dec.x = cx - 0.5f * pw;
    dec.y = cy - 0.5f * ph;
    dec.z = cx + 0.5f * pw;
    dec.w = cy + 0.5f * ph;

    ((float4*)out)[idx] = dec;                       // decoded  [B,N,4]
    ((float4*)(out + 4 * BB * NN))[idx] = tgt;       // targets  [B,N,4]
    (out + 8 * BB * NN)[idx] = (float)match;         // matches  [B,N]
}

// Single-proposal matcher (2 half-streams) + epilogue; used by remainder lanes.
__device__ __forceinline__ void process_one(const float4* __restrict__ prop_b,
                                            const float4* __restrict__ del_b,
                                            const float4* __restrict__ sg,
                                            const float*  __restrict__ sS,
                                            const int n, const int bofs,
                                            float* __restrict__ out)
{
    const float4 p  = prop_b[n];
    const float  Ap = __fmul_rn(__fsub_rn(p.z, p.x), __fsub_rn(p.w, p.y));

    Best a, c;
    iou_id(sg[0],  sS[0],  p, Ap, a.I, a.D); a.i = 0;
    iou_id(sg[HM], sS[HM], p, Ap, c.I, c.D); c.i = HM;

    #pragma unroll 4
    for (int k = 1; k < HM; k++) {
        float in, dn;
        iou_id(sg[k], sS[k], p, Ap, in, dn);
        upd(a, in, dn, k);
        iou_id(sg[HM + k], sS[HM + k], p, Ap, in, dn);
        upd(c, in, dn, HM + k);
    }

    const Best w = merge(a, c);
    const float iou = __fdiv_rn(w.I, w.D);           // exact -> threshold bit-faithful
    const int   m   = (iou < 0.5f) ? -1 : w.i;
    const float4 mg = sg[(m < 0) ? 0 : w.i];
    epilogue(p, del_b[n], mg, m, bofs + n, out);
}

__global__ __launch_bounds__(TPB, 4)
void roihead_kernel(const float4* __restrict__ proposals,
                    const float4* __restrict__ gt,
                    const float4* __restrict__ deltas,
                    float* __restrict__ out)
{
    __shared__ float4 sg[MM];
    __shared__ float  sS[MM];

    const int b   = blockIdx.y;
    const int tid = threadIdx.x;

    if (tid < MM) {
        const float4 g = gt[b * MM + tid];
        sg[tid] = g;
        sS[tid] = __fmul_rn(__fsub_rn(g.z, g.x), __fsub_rn(g.w, g.y));
    }
    __syncthreads();

    const int base = blockIdx.x * CHUNK;
    const int bofs = b * NN;
    const float4* prop_b = proposals + bofs;
    const float4* del_b  = deltas    + bofs;

    // ---- pair phase: 2 proposals/thread x 2 gt-halves = 4 independent argmax streams.
    //      No bounds checks needed: max index = 147*676 + 256 + 255 = 99883 < 100000.
    {
        const int n0 = base + tid;
        const int n1 = base + TPB + tid;

        const float4 p0 = prop_b[n0];
        const float4 p1 = prop_b[n1];
        const float Ap0 = __fmul_rn(__fsub_rn(p0.z, p0.x), __fsub_rn(p0.w, p0.y));
        const float Ap1 = __fmul_rn(__fsub_rn(p1.z, p1.x), __fsub_rn(p1.w, p1.y));

        Best a0, c0, a1, c1;
        {
            const float4 gl = sg[0];  const float Sl = sS[0];
            const float4 gh = sg[HM]; const float Sh = sS[HM];
            iou_id(gl, Sl, p0, Ap0, a0.I, a0.D); a0.i = 0;
            iou_id(gl, Sl, p1, Ap1, a1.I, a1.D); a1.i = 0;
            iou_id(gh, Sh, p0, Ap0, c0.I, c0.D); c0.i = HM;
            iou_id(gh, Sh, p1, Ap1, c1.I, c1.D); c1.i = HM;
        }

        #pragma unroll 4
        for (int k = 1; k < HM; k++) {
            const float4 gl = sg[k];      const float Sl = sS[k];
            const float4 gh = sg[HM + k]; const float Sh = sS[HM + k];

            float in, dn;
            iou_id(gl, Sl, p0, Ap0, in, dn); upd(a0, in, dn, k);
            iou_id(gl, Sl, p1, Ap1, in, dn); upd(a1, in, dn, k);
            iou_id(gh, Sh, p0, Ap0, in, dn); upd(c0, in, dn, HM + k);
            iou_id(gh, Sh, p1, Ap1, in, dn); upd(c1, in, dn, HM + k);
        }

        const Best w0 = merge(a0, c0);
        const Best w1 = merge(a1, c1);

        const float iou0 = __fdiv_rn(w0.I, w0.D);    // exact winner division
        const float iou1 = __fdiv_rn(w1.I, w1.D);

        // FG_THRESH == BG_THRESH == 0.5 -> BETWEEN(-2) unreachable.
        const int m0 = (iou0 < 0.5f) ? -1 : w0.i;
        const int m1 = (iou1 < 0.5f) ? -1 : w1.i;

        const float4 mg0 = sg[(m0 < 0) ? 0 : w0.i];  // jnp.clip(matches, 0) gather
        const float4 mg1 = sg[(m1 < 0) ? 0 : w1.i];

        epilogue(p0, del_b[n0], mg0, m0, bofs + n0, out);
        epilogue(p1, del_b[n1], mg1, m1, bofs + n1, out);
    }

    // ---- remainder phase: 164 lanes handle one more proposal each ----
    if (tid < REM) {
        const int n2 = base + 2 * TPB + tid;
        if (n2 < NN)
            process_one(prop_b, del_b, sg, sS, n2, bofs, out);
    }
}

extern "C" void kernel_launch(void* const* d_in, const int* in_sizes, int n_in,
                              void* d_out, int out_size)
{
    const float4* proposals = (const float4*)d_in[0];
    const float4* gt        = (const float4*)d_in[1];
    const float4* deltas    = (const float4*)d_in[2];
    float* out = (float*)d_out;

    dim3 grid(BPI, BB);
    roihead_kernel<<<grid, TPB>>>(proposals, gt, deltas, out);
}